// round 15
// baseline (speedup 1.0000x reference)
#include <cuda_runtime.h>

// ---------------------------------------------------------------------------
// 2-layer LSTM decoder via TF32 MMA. Round-15 = R14 (proven 2220us) with
// phase-overlapped cp.async prologues (stage next GEMM's first 2 kc during
// the previous epilogue/PROJ phase -- stages are per-warp private, no barrier
// hazard), PROJ unroll 4, streaming cache hints, conflict-free c stride.
// 256 CTAs x 32 batch rows x 512 threads.
// ---------------------------------------------------------------------------

#define T_STEPS 20
#define AS 516     // A2 smem row stride: conflict-free A-frag reads
#define CS 257     // c row stride: 257 mod 32 = 1 -> conflict-free
#define PS 164

__device__ __forceinline__ float sigf(float x)  { return __fdividef(1.f, 1.f + __expf(-x)); }
__device__ __forceinline__ float tanhe(float x) { return __fdividef(2.f, 1.f + __expf(-2.f * x)) - 1.f; }
__device__ __forceinline__ unsigned tf32r(float x) {
    unsigned r; asm("cvt.rna.tf32.f32 %0, %1;" : "=r"(r) : "f"(x)); return r;
}
__device__ __forceinline__ void mma_tf32(float* d, unsigned a0, unsigned a1, unsigned a2,
                                         unsigned a3, unsigned b0, unsigned b1) {
    asm volatile(
        "mma.sync.aligned.m16n8k8.row.col.f32.tf32.tf32.f32 "
        "{%0,%1,%2,%3}, {%4,%5,%6,%7}, {%8,%9}, {%0,%1,%2,%3};"
        : "+f"(d[0]), "+f"(d[1]), "+f"(d[2]), "+f"(d[3])
        : "r"(a0), "r"(a1), "r"(a2), "r"(a3), "r"(b0), "r"(b1));
}
__device__ __forceinline__ void cpa16(unsigned dst, const void* src) {
    asm volatile("cp.async.cg.shared.global [%0], [%1], 16;" :: "r"(dst), "l"(src));
}
#define CP_COMMIT() asm volatile("cp.async.commit_group;")
#define CP_WAIT1()  asm volatile("cp.async.wait_group 1;")
#define CP_WAIT0()  asm volatile("cp.async.wait_group 0;")

// GEMM weights, TILE-LINEAR tf32 layout (verified R14):
//   idx = kc*8192 + w*512 + j*128 + lane*4 + e
__device__ unsigned g_u1t [256 * 1024];     // U1 (32 kc)
__device__ unsigned g_w2t [512 * 1024];     // [W2;U2] (64 kc)
__device__ unsigned g_pwt [256 * 160];      // [Wmu|Wlv] perm16 layout
__device__ float    g_b2p [1024];
__device__ float    g_pb  [160];
__device__ float4   g_w1q [64 * 256];
__device__ float    g_xw1p[8192u * 1024u];  // xw1 [row][n'] fp32

__global__ void repack_kernel(const float* __restrict__ W1, const float* __restrict__ U1,
                              const float* __restrict__ W2, const float* __restrict__ U2,
                              const float* __restrict__ Wmu, const float* __restrict__ Wlv,
                              const float* __restrict__ b2,  const float* __restrict__ bmu,
                              const float* __restrict__ blv) {
    int i = blockIdx.x * blockDim.x + threadIdx.x;   // 0 .. 512*1024-1
    {
        int kc   = i >> 13;
        int rem  = i & 8191;
        int w    = rem >> 9;
        int rem2 = rem & 511;
        int j    = rem2 >> 7;
        int le   = rem2 & 127;
        int l    = le >> 2, e = le & 3;
        int q    = l & 3,  lr = l >> 2;
        int row  = kc * 8 + q + ((j >> 1) ? 4 : 0);
        int np   = w * 64 + (j & 1) * 32 + e * 8 + lr;
        int g = np & 3, u = np >> 2;
        if (row < 256)
            g_u1t[i] = tf32r(U1[row * 1024 + g * 256 + u]);
        g_w2t[i] = tf32r(row < 256 ? W2[row * 1024 + g * 256 + u]
                                   : U2[(row - 256) * 1024 + g * 256 + u]);
    }
    {
        int k2 = i >> 10, np = i & 1023;
        if (k2 < 256 && np < 160) {
            int pf = (np & ~15) + ((np & 7) * 2) + ((np & 15) >> 3);
            g_pwt[k2 * 160 + pf] = tf32r(np < 80 ? Wmu[k2 * 80 + np]
                                                 : Wlv[k2 * 80 + np - 80]);
        }
    }
    if (i < 64 * 256) {
        const float* r = W1 + (i >> 8) * 1024;
        int uu = i & 255;
        g_w1q[i] = make_float4(r[uu], r[256 + uu], r[512 + uu], r[768 + uu]);
    }
    if (i < 1024) g_b2p[i] = b2[(i & 3) * 256 + (i >> 2)];
    if (i < 160)  g_pb[i]  = (i < 80) ? bmu[i] : blv[i - 80];
}

__global__ void xw1_kernel(const float* __restrict__ z1, const float* __restrict__ z2,
                           const float* __restrict__ b1) {
    __shared__ float zt[8][64];
    const int tid = threadIdx.x;
    const int rb  = blockIdx.x * 8;
    for (int i = tid; i < 512; i += 256) {
        int r = i >> 6, k = i & 63;
        zt[r][k] = (k < 32) ? z1[(rb + r) * 32 + k] : z2[(rb + r) * 32 + (k - 32)];
    }
    __syncthreads();
    const int u = tid;
    float4 acc[8];
    #pragma unroll
    for (int r = 0; r < 8; r++) acc[r] = make_float4(0.f, 0.f, 0.f, 0.f);
    for (int k = 0; k < 64; k++) {
        float4 w = g_w1q[k * 256 + u];
        #pragma unroll
        for (int r = 0; r < 8; r++) {
            float zv = zt[r][k];
            acc[r].x += zv * w.x; acc[r].y += zv * w.y;
            acc[r].z += zv * w.z; acc[r].w += zv * w.w;
        }
    }
    float4 bq = make_float4(b1[u], b1[256 + u], b1[512 + u], b1[768 + u]);
    #pragma unroll
    for (int r = 0; r < 8; r++) {
        float4 o = make_float4(acc[r].x + bq.x, acc[r].y + bq.y,
                               acc[r].z + bq.z, acc[r].w + bq.w);
        *(float4*)(g_xw1p + (size_t)(rb + r) * 1024 + 4 * u) = o;
    }
}

// SMEM: A2 [32][AS] | c1s/c2s [32][CS] | prj [32][PS] | B stages 2x32KB
#define SMEM_CORE   (32 * AS + 2 * 32 * CS + 32 * PS)
#define SMEM_FLOATS (SMEM_CORE + 2 * 8192)
#define SMEM_BYTES  (SMEM_FLOATS * 4)

// Stage kc s (buffer s&1) of B for this warp; one commit group.
__device__ __forceinline__ void stage_kc(const unsigned* __restrict__ B, int s,
                                         unsigned sdst, int w, int lane) {
    const unsigned* src = B + (size_t)s * 8192 + w * 512 + lane * 4;
    unsigned dst = sdst + (s & 1) * 32768;
    #pragma unroll
    for (int p = 0; p < 4; p++)
        cpa16(dst + p * 512, src + p * 128);
    CP_COMMIT();
}

// Pipelined GEMM main loop (prologue for kc0/kc1 must already be committed).
__device__ __forceinline__ void gemm_main(
    float acc[8][2][4], const float* __restrict__ A2s,
    const unsigned* __restrict__ B, int KC,
    unsigned sdst, int w, int lane, int lr, int q)
{
    const unsigned* gsrc = B + w * 512 + lane * 4;
    #pragma unroll 1
    for (int kc = 0; kc < KC; kc++) {
        CP_WAIT1();
        unsigned sbuf = sdst + (kc & 1) * 32768;
        uint4 b0A, b0B, b1A, b1B;
        asm volatile("ld.shared.v4.u32 {%0,%1,%2,%3}, [%4];"
            : "=r"(b0A.x), "=r"(b0A.y), "=r"(b0A.z), "=r"(b0A.w) : "r"(sbuf));
        asm volatile("ld.shared.v4.u32 {%0,%1,%2,%3}, [%4];"
            : "=r"(b0B.x), "=r"(b0B.y), "=r"(b0B.z), "=r"(b0B.w) : "r"(sbuf + 512));
        asm volatile("ld.shared.v4.u32 {%0,%1,%2,%3}, [%4];"
            : "=r"(b1A.x), "=r"(b1A.y), "=r"(b1A.z), "=r"(b1A.w) : "r"(sbuf + 1024));
        asm volatile("ld.shared.v4.u32 {%0,%1,%2,%3}, [%4];"
            : "=r"(b1B.x), "=r"(b1B.y), "=r"(b1B.z), "=r"(b1B.w) : "r"(sbuf + 1536));
        if (kc + 2 < KC) {
            const unsigned* src = gsrc + (size_t)(kc + 2) * 8192;
            #pragma unroll
            for (int p = 0; p < 4; p++)
                cpa16(sbuf + p * 512, src + p * 128);
        }
        CP_COMMIT();

        int kb = kc * 8;
        unsigned a[2][4];
        #pragma unroll
        for (int mt = 0; mt < 2; mt++) {
            const float* ar = A2s + (mt * 16 + lr) * AS + kb + q;
            a[mt][0] = __float_as_uint(ar[0]);
            a[mt][1] = __float_as_uint(ar[8 * AS]);
            a[mt][2] = __float_as_uint(ar[4]);
            a[mt][3] = __float_as_uint(ar[8 * AS + 4]);
        }
        #pragma unroll
        for (int mt = 0; mt < 2; mt++) {
            mma_tf32(acc[0][mt], a[mt][0], a[mt][1], a[mt][2], a[mt][3], b0A.x, b1A.x);
            mma_tf32(acc[1][mt], a[mt][0], a[mt][1], a[mt][2], a[mt][3], b0A.y, b1A.y);
            mma_tf32(acc[2][mt], a[mt][0], a[mt][1], a[mt][2], a[mt][3], b0A.z, b1A.z);
            mma_tf32(acc[3][mt], a[mt][0], a[mt][1], a[mt][2], a[mt][3], b0A.w, b1A.w);
            mma_tf32(acc[4][mt], a[mt][0], a[mt][1], a[mt][2], a[mt][3], b0B.x, b1B.x);
            mma_tf32(acc[5][mt], a[mt][0], a[mt][1], a[mt][2], a[mt][3], b0B.y, b1B.y);
            mma_tf32(acc[6][mt], a[mt][0], a[mt][1], a[mt][2], a[mt][3], b0B.z, b1B.z);
            mma_tf32(acc[7][mt], a[mt][0], a[mt][1], a[mt][2], a[mt][3], b0B.w, b1B.w);
        }
    }
    CP_WAIT0();
}

__global__ void __launch_bounds__(512, 1) lstm_kernel(
    const float* __restrict__ eps, float* __restrict__ out)
{
    extern __shared__ float sm[];
    float* A2  = sm;                    // [32][AS]
    float* c1s = sm + 32 * AS;          // [32][CS]
    float* c2s = c1s + 32 * CS;
    float* prj = c2s + 32 * CS;         // [32][PS]
    float* stg = sm + SMEM_CORE;        // 2 x 32KB B stages
    const unsigned sbase = (unsigned)__cvta_generic_to_shared(stg);

    const int tid  = threadIdx.x;
    const int w    = tid >> 5;          // 0..15
    const int lane = tid & 31;
    const int q    = lane & 3;
    const int lr   = lane >> 2;
    const int rb   = blockIdx.x * 32;
    const int wb   = w * 64;
    const bool qe  = !(q & 1);
    const unsigned sdst = sbase + w * 2048 + lane * 16;

    for (int i = tid; i < SMEM_CORE; i += 512) sm[i] = 0.f;
    __syncthreads();

    float acc[8][2][4];

    // prologue for step 0 GEMM1
    stage_kc(g_u1t, 0, sdst, w, lane);
    stage_kc(g_u1t, 1, sdst, w, lane);

    for (int t = 0; t < T_STEPS; t++) {
        // ===================== GEMM1: h1old @ U1 =====================
        #pragma unroll
        for (int nt = 0; nt < 8; nt++)
            #pragma unroll
            for (int mt = 0; mt < 2; mt++)
                acc[nt][mt][0] = acc[nt][mt][1] = acc[nt][mt][2] = acc[nt][mt][3] = 0.f;
        gemm_main(acc, A2, g_u1t, 32, sdst, w, lane, lr, q);
        __syncthreads();                                 // (1) A2 h1 reads done

        // ----- epilogue 1 (GEMM2 prologue overlapped) -----
        stage_kc(g_w2t, 0, sdst, w, lane);
        stage_kc(g_w2t, 1, sdst, w, lane);
        #pragma unroll
        for (int nt = 0; nt < 8; nt++) {
            #pragma unroll
            for (int mt = 0; mt < 2; mt++) {
                float* d = acc[nt][mt];
                int cb = wb + nt * 8 + q * 2;
                int R0 = mt * 16 + lr, R1 = R0 + 8;
                float2 x0 = *(const float2*)(g_xw1p + (size_t)(rb + R0) * 1024 + cb);
                float2 x1 = *(const float2*)(g_xw1p + (size_t)(rb + R1) * 1024 + cb);
                d[0] += x0.x; d[1] += x0.y; d[2] += x1.x; d[3] += x1.y;
                float s0, s1, s2, s3;
                if (q & 1) { s0 = tanhe(d[0]); s1 = sigf(d[1]); s2 = tanhe(d[2]); s3 = sigf(d[3]); }
                else       { s0 = sigf(d[0]);  s1 = sigf(d[1]); s2 = sigf(d[2]);  s3 = sigf(d[3]); }
                float r0 = __shfl_xor_sync(~0u, s0, 1);
                float r1 = __shfl_xor_sync(~0u, s1, 1);
                float r2 = __shfl_xor_sync(~0u, s2, 1);
                float r3 = __shfl_xor_sync(~0u, s3, 1);
                if (qe) {   // owns (i,f); receives (g,o)
                    int u = w * 16 + nt * 2 + (q >> 1);
                    float cn0 = s1 * c1s[R0 * CS + u] + s0 * r0;
                    c1s[R0 * CS + u] = cn0;
                    A2[R0 * AS + u] = __uint_as_float(tf32r(r1 * tanhe(cn0)));
                    float cn1 = s3 * c1s[R1 * CS + u] + s2 * r2;
                    c1s[R1 * CS + u] = cn1;
                    A2[R1 * AS + u] = __uint_as_float(tf32r(r3 * tanhe(cn1)));
                }
            }
        }
        __syncthreads();                                 // (2) h1new visible

        // ============ GEMM2: [h1new|h2old] @ [W2;U2] ============
        #pragma unroll
        for (int nt = 0; nt < 8; nt++)
            #pragma unroll
            for (int mt = 0; mt < 2; mt++)
                acc[nt][mt][0] = acc[nt][mt][1] = acc[nt][mt][2] = acc[nt][mt][3] = 0.f;
        gemm_main(acc, A2, g_w2t, 64, sdst, w, lane, lr, q);
        __syncthreads();                                 // (3) A2 reads done

        // ----- epilogue 2: + b2, gates, c2/h2 update, h2 -> out -----
        #pragma unroll
        for (int nt = 0; nt < 8; nt++) {
            #pragma unroll
            for (int mt = 0; mt < 2; mt++) {
                float* d = acc[nt][mt];
                int cb = wb + nt * 8 + q * 2;
                int R0 = mt * 16 + lr, R1 = R0 + 8;
                float2 bb = *(const float2*)(g_b2p + cb);
                d[0] += bb.x; d[1] += bb.y; d[2] += bb.x; d[3] += bb.y;
                float s0, s1, s2, s3;
                if (q & 1) { s0 = tanhe(d[0]); s1 = sigf(d[1]); s2 = tanhe(d[2]); s3 = sigf(d[3]); }
                else       { s0 = sigf(d[0]);  s1 = sigf(d[1]); s2 = sigf(d[2]);  s3 = sigf(d[3]); }
                float r0 = __shfl_xor_sync(~0u, s0, 1);
                float r1 = __shfl_xor_sync(~0u, s1, 1);
                float r2 = __shfl_xor_sync(~0u, s2, 1);
                float r3 = __shfl_xor_sync(~0u, s3, 1);
                if (qe) {
                    int u = w * 16 + nt * 2 + (q >> 1);
                    float cn0 = s1 * c2s[R0 * CS + u] + s0 * r0;
                    c2s[R0 * CS + u] = cn0;
                    float h0 = r1 * tanhe(cn0);
                    A2[R0 * AS + 256 + u] = __uint_as_float(tf32r(h0));
                    float cn1 = s3 * c2s[R1 * CS + u] + s2 * r2;
                    c2s[R1 * CS + u] = cn1;
                    float h1 = r3 * tanhe(cn1);
                    A2[R1 * AS + 256 + u] = __uint_as_float(tf32r(h1));
                    __stcs(&out[((size_t)(rb + R0) * T_STEPS + t) * 256 + u], h0);
                    __stcs(&out[((size_t)(rb + R1) * T_STEPS + t) * 256 + u], h1);
                }
            }
        }
        __syncthreads();                                 // (4) h2new visible

        // ----- next step's GEMM1 prologue, overlapped with PROJ+sampler -----
        if (t + 1 < T_STEPS) {
            stage_kc(g_u1t, 0, sdst, w, lane);
            stage_kc(g_u1t, 1, sdst, w, lane);
        }

        // =============== PROJ: h2new @ [Wmu|Wlv] (warps 0-9) ===============
        if (w < 10) {
            float pa[2][2][4];
            #pragma unroll
            for (int nt = 0; nt < 2; nt++)
                #pragma unroll
                for (int mt = 0; mt < 2; mt++)
                    pa[nt][mt][0] = pa[nt][mt][1] = pa[nt][mt][2] = pa[nt][mt][3] = 0.f;
            #pragma unroll 4
            for (int kc = 0; kc < 32; kc++) {
                int kb = kc * 8;
                uint2 b0v = *(const uint2*)(g_pwt + (kb + q) * 160 + w * 16 + lr * 2);
                uint2 b1v = *(const uint2*)(g_pwt + (kb + q + 4) * 160 + w * 16 + lr * 2);
                unsigned a[2][4];
                #pragma unroll
                for (int mt = 0; mt < 2; mt++) {
                    const float* ar = A2 + (mt * 16 + lr) * AS + 256 + kb + q;
                    a[mt][0] = __float_as_uint(ar[0]);
                    a[mt][1] = __float_as_uint(ar[8 * AS]);
                    a[mt][2] = __float_as_uint(ar[4]);
                    a[mt][3] = __float_as_uint(ar[8 * AS + 4]);
                }
                #pragma unroll
                for (int mt = 0; mt < 2; mt++) {
                    mma_tf32(pa[0][mt], a[mt][0], a[mt][1], a[mt][2], a[mt][3], b0v.x, b1v.x);
                    mma_tf32(pa[1][mt], a[mt][0], a[mt][1], a[mt][2], a[mt][3], b0v.y, b1v.y);
                }
            }
            #pragma unroll
            for (int nt = 0; nt < 2; nt++) {
                #pragma unroll
                for (int mt = 0; mt < 2; mt++) {
                    int col = w * 16 + nt * 8 + q * 2;
                    int R0 = mt * 16 + lr, R1 = R0 + 8;
                    float2 pb = *(const float2*)(g_pb + col);
                    prj[R0 * PS + col]     = pa[nt][mt][0] + pb.x;
                    prj[R0 * PS + col + 1] = pa[nt][mt][1] + pb.y;
                    prj[R1 * PS + col]     = pa[nt][mt][2] + pb.x;
                    prj[R1 * PS + col + 1] = pa[nt][mt][3] + pb.y;
                }
            }
        }
        __syncthreads();                                 // (5) prj ready

        // ---- sampler ----
        #pragma unroll
        for (int j = 0; j < 5; j++) {
            int i = tid + j * 512;
            int r = i / 80, f = i - r * 80;
            float mu = prj[r * PS + f];
            float lv = prj[r * PS + f + 80];
            size_t base = ((size_t)(rb + r) * T_STEPS + t) * 80 + f;
            float e = __ldcs(&eps[base]);
            __stcs(&out[41943040u + base], mu);
            __stcs(&out[55050240u + base], lv);
            __stcs(&out[68157440u + base], e * __expf(0.5f * mu) + lv);
        }
    }
}

extern "C" void kernel_launch(void* const* d_in, const int* in_sizes, int n_in,
                              void* d_out, int out_size) {
    // order: x, z1, z2, eps, W1, U1, b1, W2, U2, b2, Wmu, bmu, Wlv, blv
    const float* z1  = (const float*)d_in[1];
    const float* z2  = (const float*)d_in[2];
    const float* eps = (const float*)d_in[3];
    const float* W1  = (const float*)d_in[4];
    const float* U1  = (const float*)d_in[5];
    const float* b1  = (const float*)d_in[6];
    const float* W2  = (const float*)d_in[7];
    const float* U2  = (const float*)d_in[8];
    const float* b2  = (const float*)d_in[9];
    const float* Wmu = (const float*)d_in[10];
    const float* bmu = (const float*)d_in[11];
    const float* Wlv = (const float*)d_in[12];
    const float* blv = (const float*)d_in[13];
    float* out = (float*)d_out;

    cudaFuncSetAttribute(lstm_kernel, cudaFuncAttributeMaxDynamicSharedMemorySize, SMEM_BYTES);

    repack_kernel<<<512, 1024>>>(W1, U1, W2, U2, Wmu, Wlv, b2, bmu, blv);
    xw1_kernel<<<1024, 256>>>(z1, z2, b1);
    lstm_kernel<<<256, 512, SMEM_BYTES>>>(eps, out);
}

// round 16
// speedup vs baseline: 1.5748x; 1.5748x over previous
#include <cuda_runtime.h>
#include <cuda_fp16.h>

// ---------------------------------------------------------------------------
// 2-layer LSTM decoder via FP16 tensor-core MMA (mma.sync.m16n8k16.f16, fp32
// accum). Round-16 = R14 chassis (proven 2220us: tile-linear weights,
// per-warp cp.async 2-stage pipeline, 512 thr, 256 CTAs x 32 rows) with the
// datapath halved: fp16 weights & h (same 10-bit mantissa as tf32 -> same
// precision), K=16 per kc -> half the bytes, mma ops, and A-frag LDS.
// ---------------------------------------------------------------------------

#define T_STEPS 20
#define AH 520     // A2 half-stride per row: lr*260+q mod 32 distinct -> conflict-free
#define CS 264
#define PS 164

__device__ __forceinline__ float sigf(float x)  { return __fdividef(1.f, 1.f + __expf(-x)); }
__device__ __forceinline__ float tanhe(float x) { return __fdividef(2.f, 1.f + __expf(-2.f * x)) - 1.f; }
__device__ __forceinline__ void mma_f16(float* d, unsigned a0, unsigned a1, unsigned a2,
                                        unsigned a3, unsigned b0, unsigned b1) {
    asm volatile(
        "mma.sync.aligned.m16n8k16.row.col.f32.f16.f16.f32 "
        "{%0,%1,%2,%3}, {%4,%5,%6,%7}, {%8,%9}, {%0,%1,%2,%3};"
        : "+f"(d[0]), "+f"(d[1]), "+f"(d[2]), "+f"(d[3])
        : "r"(a0), "r"(a1), "r"(a2), "r"(a3), "r"(b0), "r"(b1));
}
__device__ __forceinline__ void cpa16(unsigned dst, const void* src) {
    asm volatile("cp.async.cg.shared.global [%0], [%1], 16;" :: "r"(dst), "l"(src));
}
#define CP_COMMIT() asm volatile("cp.async.commit_group;")
#define CP_WAIT1()  asm volatile("cp.async.wait_group 1;")
#define CP_WAIT0()  asm volatile("cp.async.wait_group 0;")
__device__ __forceinline__ unsigned h2pack(float lo, float hi) {
    __half2 h = __floats2half2_rn(lo, hi);
    return *reinterpret_cast<unsigned*>(&h);
}

// GEMM weights, TILE-LINEAR fp16 layout. Unit = uint (half2 = 2 K-rows):
//   idx = kc*8192 + w*512 + j*128 + lane*4 + e      (kc covers K=16)
//   j: 0=b0/grpA 1=b0/grpB 2=b1/grpA 3=b1/grpB
//   rows = kc*16 + 2*(lane&3) + (j>=2 ? 8 : 0) + {0,1}
//   col n' = w*64 + (j&1)*32 + e*8 + (lane>>2),  n' = unit*4 + gate
__device__ unsigned g_u1h [16 * 8192];      // U1 (16 kc)
__device__ unsigned g_w2h [32 * 8192];      // [W2;U2] (32 kc)
__device__ uint4    g_pwh [16 * 320];       // proj [kc][w(10)][lane]: {b0n0,b0n1,b1n0,b1n1}
__device__ float    g_b2p [1024];
__device__ float    g_pb  [160];
__device__ float4   g_w1q [64 * 256];
__device__ float    g_xw1p[8192u * 1024u];  // xw1 [row][n'] fp32

__global__ void repack_kernel(const float* __restrict__ W1, const float* __restrict__ U1,
                              const float* __restrict__ W2, const float* __restrict__ U2,
                              const float* __restrict__ Wmu, const float* __restrict__ Wlv,
                              const float* __restrict__ b2,  const float* __restrict__ bmu,
                              const float* __restrict__ blv) {
    int i = blockIdx.x * blockDim.x + threadIdx.x;   // 0 .. 524287
    if (i < 32 * 8192) {
        int kc   = i >> 13;
        int rem  = i & 8191;
        int w    = rem >> 9;
        int rem2 = rem & 511;
        int j    = rem2 >> 7;
        int le   = rem2 & 127;
        int lane = le >> 2, e = le & 3;
        int q    = lane & 3, lr = lane >> 2;
        int row  = kc * 16 + 2 * q + ((j >> 1) ? 8 : 0);
        int np   = w * 64 + (j & 1) * 32 + e * 8 + lr;
        int g = np & 3, u = np >> 2;
        if (kc < 16) {
            float lo = U1[row * 1024 + g * 256 + u];
            float hi = U1[(row + 1) * 1024 + g * 256 + u];
            g_u1h[i] = h2pack(lo, hi);
        }
        float lo, hi;
        if (row < 256) {
            lo = W2[row * 1024 + g * 256 + u];
            hi = W2[(row + 1) * 1024 + g * 256 + u];
        } else {
            lo = U2[(row - 256) * 1024 + g * 256 + u];
            hi = U2[(row - 255) * 1024 + g * 256 + u];
        }
        g_w2h[i] = h2pack(lo, hi);
    }
    if (i < 16 * 320) {
        int kc = i / 320, rem = i % 320;
        int w = rem / 32, lane = rem % 32;
        int q = lane & 3, lr = lane >> 2;
        uint4 v;
        #pragma unroll
        for (int nt = 0; nt < 2; nt++) {
            int col = w * 16 + nt * 8 + lr;
            const float* P = (col < 80) ? Wmu : Wlv;
            int f = (col < 80) ? col : col - 80;
            int r0 = kc * 16 + 2 * q;
            unsigned v0 = h2pack(P[r0 * 80 + f],       P[(r0 + 1) * 80 + f]);
            unsigned v1 = h2pack(P[(r0 + 8) * 80 + f], P[(r0 + 9) * 80 + f]);
            if (nt == 0) { v.x = v0; v.z = v1; } else { v.y = v0; v.w = v1; }
        }
        g_pwh[i] = v;
    }
    if (i < 64 * 256) {
        const float* r = W1 + (i >> 8) * 1024;
        int uu = i & 255;
        g_w1q[i] = make_float4(r[uu], r[256 + uu], r[512 + uu], r[768 + uu]);
    }
    if (i < 1024) g_b2p[i] = b2[(i & 3) * 256 + (i >> 2)];
    if (i < 160)  g_pb[i]  = (i < 80) ? bmu[i] : blv[i - 80];
}

__global__ void xw1_kernel(const float* __restrict__ z1, const float* __restrict__ z2,
                           const float* __restrict__ b1) {
    __shared__ float zt[8][64];
    const int tid = threadIdx.x;
    const int rb  = blockIdx.x * 8;
    for (int i = tid; i < 512; i += 256) {
        int r = i >> 6, k = i & 63;
        zt[r][k] = (k < 32) ? z1[(rb + r) * 32 + k] : z2[(rb + r) * 32 + (k - 32)];
    }
    __syncthreads();
    const int u = tid;
    float4 acc[8];
    #pragma unroll
    for (int r = 0; r < 8; r++) acc[r] = make_float4(0.f, 0.f, 0.f, 0.f);
    for (int k = 0; k < 64; k++) {
        float4 w = g_w1q[k * 256 + u];
        #pragma unroll
        for (int r = 0; r < 8; r++) {
            float zv = zt[r][k];
            acc[r].x += zv * w.x; acc[r].y += zv * w.y;
            acc[r].z += zv * w.z; acc[r].w += zv * w.w;
        }
    }
    float4 bq = make_float4(b1[u], b1[256 + u], b1[512 + u], b1[768 + u]);
    #pragma unroll
    for (int r = 0; r < 8; r++) {
        float4 o = make_float4(acc[r].x + bq.x, acc[r].y + bq.y,
                               acc[r].z + bq.z, acc[r].w + bq.w);
        *(float4*)(g_xw1p + (size_t)(rb + r) * 1024 + 4 * u) = o;
    }
}

// SMEM: A2h [32 rows][AH halves] | c1s/c2s [32][CS] | prj [32][PS] | 2x32KB stages
#define A2_FLOATS  (32 * AH / 2)
#define SMEM_CORE  (A2_FLOATS + 2 * 32 * CS + 32 * PS)
#define SMEM_FLOATS (SMEM_CORE + 2 * 8192)
#define SMEM_BYTES  (SMEM_FLOATS * 4)

// Pipelined GEMM: acc += A2h[., k] * B[k][warp's 64 cols], K = KC*16.
// acol in halves (0 for h1, 256 for h2 region).
__device__ __forceinline__ void gemm_pipe(
    float acc[8][2][4], const __half* __restrict__ A2h, int acol,
    const unsigned* __restrict__ B, int KC,
    unsigned sdst, int w, int lane, int lr, int q)
{
    const unsigned* gsrc = B + w * 512 + lane * 4;

    #pragma unroll
    for (int s = 0; s < 2; s++) {
        const unsigned* src = gsrc + s * 8192;
        unsigned dst = sdst + s * 32768;
        #pragma unroll
        for (int p = 0; p < 4; p++)
            cpa16(dst + p * 512, src + p * 128);
        CP_COMMIT();
    }

    #pragma unroll 1
    for (int kc = 0; kc < KC; kc++) {
        CP_WAIT1();
        unsigned sbuf = sdst + (kc & 1) * 32768;
        uint4 b0A, b0B, b1A, b1B;
        asm volatile("ld.shared.v4.u32 {%0,%1,%2,%3}, [%4];"
            : "=r"(b0A.x), "=r"(b0A.y), "=r"(b0A.z), "=r"(b0A.w) : "r"(sbuf));
        asm volatile("ld.shared.v4.u32 {%0,%1,%2,%3}, [%4];"
            : "=r"(b0B.x), "=r"(b0B.y), "=r"(b0B.z), "=r"(b0B.w) : "r"(sbuf + 512));
        asm volatile("ld.shared.v4.u32 {%0,%1,%2,%3}, [%4];"
            : "=r"(b1A.x), "=r"(b1A.y), "=r"(b1A.z), "=r"(b1A.w) : "r"(sbuf + 1024));
        asm volatile("ld.shared.v4.u32 {%0,%1,%2,%3}, [%4];"
            : "=r"(b1B.x), "=r"(b1B.y), "=r"(b1B.z), "=r"(b1B.w) : "r"(sbuf + 1536));
        if (kc + 2 < KC) {
            const unsigned* src = gsrc + (size_t)(kc + 2) * 8192;
            #pragma unroll
            for (int p = 0; p < 4; p++)
                cpa16(sbuf + p * 512, src + p * 128);
        }
        CP_COMMIT();

        int kb = kc * 16;
        unsigned a[2][4];
        #pragma unroll
        for (int mt = 0; mt < 2; mt++) {
            const __half* ar = A2h + (mt * 16 + lr) * AH + acol + kb + 2 * q;
            a[mt][0] = *(const unsigned*)(ar);              // rows lr,   k 2q..2q+1
            a[mt][1] = *(const unsigned*)(ar + 8 * AH);     // rows lr+8
            a[mt][2] = *(const unsigned*)(ar + 8);          // k +8
            a[mt][3] = *(const unsigned*)(ar + 8 * AH + 8);
        }
        #pragma unroll
        for (int mt = 0; mt < 2; mt++) {
            mma_f16(acc[0][mt], a[mt][0], a[mt][1], a[mt][2], a[mt][3], b0A.x, b1A.x);
            mma_f16(acc[1][mt], a[mt][0], a[mt][1], a[mt][2], a[mt][3], b0A.y, b1A.y);
            mma_f16(acc[2][mt], a[mt][0], a[mt][1], a[mt][2], a[mt][3], b0A.z, b1A.z);
            mma_f16(acc[3][mt], a[mt][0], a[mt][1], a[mt][2], a[mt][3], b0A.w, b1A.w);
            mma_f16(acc[4][mt], a[mt][0], a[mt][1], a[mt][2], a[mt][3], b0B.x, b1B.x);
            mma_f16(acc[5][mt], a[mt][0], a[mt][1], a[mt][2], a[mt][3], b0B.y, b1B.y);
            mma_f16(acc[6][mt], a[mt][0], a[mt][1], a[mt][2], a[mt][3], b0B.z, b1B.z);
            mma_f16(acc[7][mt], a[mt][0], a[mt][1], a[mt][2], a[mt][3], b0B.w, b1B.w);
        }
    }
    CP_WAIT0();
}

__global__ void __launch_bounds__(512, 1) lstm_kernel(
    const float* __restrict__ eps, float* __restrict__ out)
{
    extern __shared__ float sm[];
    __half* A2h = (__half*)sm;              // [32][AH] halves
    float* c1s = sm + A2_FLOATS;            // [32][CS]
    float* c2s = c1s + 32 * CS;
    float* prj = c2s + 32 * CS;             // [32][PS]
    float* stg = sm + SMEM_CORE;
    const unsigned sbase = (unsigned)__cvta_generic_to_shared(stg);

    const int tid  = threadIdx.x;
    const int w    = tid >> 5;          // 0..15
    const int lane = tid & 31;
    const int q    = lane & 3;
    const int lr   = lane >> 2;
    const int rb   = blockIdx.x * 32;
    const int wb   = w * 64;
    const bool qe  = !(q & 1);
    const unsigned sdst = sbase + w * 2048 + lane * 16;

    for (int i = tid; i < SMEM_CORE; i += 512) sm[i] = 0.f;
    __syncthreads();

    float acc[8][2][4];

    for (int t = 0; t < T_STEPS; t++) {
        // ===================== GEMM1: h1old @ U1 =====================
        #pragma unroll
        for (int nt = 0; nt < 8; nt++)
            #pragma unroll
            for (int mt = 0; mt < 2; mt++)
                acc[nt][mt][0] = acc[nt][mt][1] = acc[nt][mt][2] = acc[nt][mt][3] = 0.f;
        gemm_pipe(acc, A2h, 0, g_u1h, 16, sdst, w, lane, lr, q);
        __syncthreads();                                 // (1) A2 h1 reads done

        // ----- epilogue 1: + xw1, gates, c1/h1 update -----
        #pragma unroll
        for (int nt = 0; nt < 8; nt++) {
            #pragma unroll
            for (int mt = 0; mt < 2; mt++) {
                float* d = acc[nt][mt];
                int cb = wb + nt * 8 + q * 2;
                int R0 = mt * 16 + lr, R1 = R0 + 8;
                float2 x0 = *(const float2*)(g_xw1p + (size_t)(rb + R0) * 1024 + cb);
                float2 x1 = *(const float2*)(g_xw1p + (size_t)(rb + R1) * 1024 + cb);
                d[0] += x0.x; d[1] += x0.y; d[2] += x1.x; d[3] += x1.y;
                float s0, s1, s2, s3;
                if (q & 1) { s0 = tanhe(d[0]); s1 = sigf(d[1]); s2 = tanhe(d[2]); s3 = sigf(d[3]); }
                else       { s0 = sigf(d[0]);  s1 = sigf(d[1]); s2 = sigf(d[2]);  s3 = sigf(d[3]); }
                float r0 = __shfl_xor_sync(~0u, s0, 1);
                float r1 = __shfl_xor_sync(~0u, s1, 1);
                float r2 = __shfl_xor_sync(~0u, s2, 1);
                float r3 = __shfl_xor_sync(~0u, s3, 1);
                if (qe) {   // owns (i,f); receives (g,o)
                    int u = w * 16 + nt * 2 + (q >> 1);
                    float cn0 = s1 * c1s[R0 * CS + u] + s0 * r0;
                    c1s[R0 * CS + u] = cn0;
                    A2h[R0 * AH + u] = __float2half_rn(r1 * tanhe(cn0));
                    float cn1 = s3 * c1s[R1 * CS + u] + s2 * r2;
                    c1s[R1 * CS + u] = cn1;
                    A2h[R1 * AH + u] = __float2half_rn(r3 * tanhe(cn1));
                }
            }
        }
        __syncthreads();                                 // (2) h1new visible

        // ============ GEMM2: [h1new|h2old] @ [W2;U2] ============
        #pragma unroll
        for (int nt = 0; nt < 8; nt++)
            #pragma unroll
            for (int mt = 0; mt < 2; mt++)
                acc[nt][mt][0] = acc[nt][mt][1] = acc[nt][mt][2] = acc[nt][mt][3] = 0.f;
        gemm_pipe(acc, A2h, 0, g_w2h, 32, sdst, w, lane, lr, q);
        __syncthreads();                                 // (3) A2 reads done

        // ----- epilogue 2: + b2, gates, c2/h2 update, h2 -> out -----
        #pragma unroll
        for (int nt = 0; nt < 8; nt++) {
            #pragma unroll
            for (int mt = 0; mt < 2; mt++) {
                float* d = acc[nt][mt];
                int cb = wb + nt * 8 + q * 2;
                int R0 = mt * 16 + lr, R1 = R0 + 8;
                float2 bb = *(const float2*)(g_b2p + cb);
                d[0] += bb.x; d[1] += bb.y; d[2] += bb.x; d[3] += bb.y;
                float s0, s1, s2, s3;
                if (q & 1) { s0 = tanhe(d[0]); s1 = sigf(d[1]); s2 = tanhe(d[2]); s3 = sigf(d[3]); }
                else       { s0 = sigf(d[0]);  s1 = sigf(d[1]); s2 = sigf(d[2]);  s3 = sigf(d[3]); }
                float r0 = __shfl_xor_sync(~0u, s0, 1);
                float r1 = __shfl_xor_sync(~0u, s1, 1);
                float r2 = __shfl_xor_sync(~0u, s2, 1);
                float r3 = __shfl_xor_sync(~0u, s3, 1);
                if (qe) {
                    int u = w * 16 + nt * 2 + (q >> 1);
                    float cn0 = s1 * c2s[R0 * CS + u] + s0 * r0;
                    c2s[R0 * CS + u] = cn0;
                    float h0 = r1 * tanhe(cn0);
                    A2h[R0 * AH + 256 + u] = __float2half_rn(h0);
                    float cn1 = s3 * c2s[R1 * CS + u] + s2 * r2;
                    c2s[R1 * CS + u] = cn1;
                    float h1 = r3 * tanhe(cn1);
                    A2h[R1 * AH + 256 + u] = __float2half_rn(h1);
                    out[((size_t)(rb + R0) * T_STEPS + t) * 256 + u] = h0;
                    out[((size_t)(rb + R1) * T_STEPS + t) * 256 + u] = h1;
                }
            }
        }
        __syncthreads();                                 // (4) h2new visible

        // =============== PROJ: h2new @ [Wmu|Wlv] (warps 0-9) ===============
        if (w < 10) {
            float pa[2][2][4];
            #pragma unroll
            for (int nt = 0; nt < 2; nt++)
                #pragma unroll
                for (int mt = 0; mt < 2; mt++)
                    pa[nt][mt][0] = pa[nt][mt][1] = pa[nt][mt][2] = pa[nt][mt][3] = 0.f;
            #pragma unroll 2
            for (int kc = 0; kc < 16; kc++) {
                uint4 bv = g_pwh[kc * 320 + w * 32 + lane];
                int kb = kc * 16;
                unsigned a[2][4];
                #pragma unroll
                for (int mt = 0; mt < 2; mt++) {
                    const __half* ar = A2h + (mt * 16 + lr) * AH + 256 + kb + 2 * q;
                    a[mt][0] = *(const unsigned*)(ar);
                    a[mt][1] = *(const unsigned*)(ar + 8 * AH);
                    a[mt][2] = *(const unsigned*)(ar + 8);
                    a[mt][3] = *(const unsigned*)(ar + 8 * AH + 8);
                }
                #pragma unroll
                for (int mt = 0; mt < 2; mt++) {
                    mma_f16(pa[0][mt], a[mt][0], a[mt][1], a[mt][2], a[mt][3], bv.x, bv.z);
                    mma_f16(pa[1][mt], a[mt][0], a[mt][1], a[mt][2], a[mt][3], bv.y, bv.w);
                }
            }
            #pragma unroll
            for (int nt = 0; nt < 2; nt++) {
                #pragma unroll
                for (int mt = 0; mt < 2; mt++) {
                    int col = w * 16 + nt * 8 + q * 2;
                    int R0 = mt * 16 + lr, R1 = R0 + 8;
                    float2 pb = *(const float2*)(g_pb + col);
                    prj[R0 * PS + col]     = pa[nt][mt][0] + pb.x;
                    prj[R0 * PS + col + 1] = pa[nt][mt][1] + pb.y;
                    prj[R1 * PS + col]     = pa[nt][mt][2] + pb.x;
                    prj[R1 * PS + col + 1] = pa[nt][mt][3] + pb.y;
                }
            }
        }
        __syncthreads();                                 // (5) prj ready

        // ---- sampler ----
        #pragma unroll
        for (int j = 0; j < 5; j++) {
            int i = tid + j * 512;
            int r = i / 80, f = i - r * 80;
            float mu = prj[r * PS + f];
            float lv = prj[r * PS + f + 80];
            size_t base = ((size_t)(rb + r) * T_STEPS + t) * 80 + f;
            float e = eps[base];
            out[41943040u + base] = mu;
            out[55050240u + base] = lv;
            out[68157440u + base] = e * __expf(0.5f * mu) + lv;
        }
    }
}

extern "C" void kernel_launch(void* const* d_in, const int* in_sizes, int n_in,
                              void* d_out, int out_size) {
    // order: x, z1, z2, eps, W1, U1, b1, W2, U2, b2, Wmu, bmu, Wlv, blv
    const float* z1  = (const float*)d_in[1];
    const float* z2  = (const float*)d_in[2];
    const float* eps = (const float*)d_in[3];
    const float* W1  = (const float*)d_in[4];
    const float* U1  = (const float*)d_in[5];
    const float* b1  = (const float*)d_in[6];
    const float* W2  = (const float*)d_in[7];
    const float* U2  = (const float*)d_in[8];
    const float* b2  = (const float*)d_in[9];
    const float* Wmu = (const float*)d_in[10];
    const float* bmu = (const float*)d_in[11];
    const float* Wlv = (const float*)d_in[12];
    const float* blv = (const float*)d_in[13];
    float* out = (float*)d_out;

    cudaFuncSetAttribute(lstm_kernel, cudaFuncAttributeMaxDynamicSharedMemorySize, SMEM_BYTES);

    repack_kernel<<<512, 1024>>>(W1, U1, W2, U2, Wmu, Wlv, b2, bmu, blv);
    xw1_kernel<<<1024, 256>>>(z1, z2, b1);
    lstm_kernel<<<256, 512, SMEM_BYTES>>>(eps, out);
}

// round 17
// speedup vs baseline: 1.5768x; 1.0013x over previous
#include <cuda_runtime.h>
#include <cuda_fp16.h>

// ---------------------------------------------------------------------------
// 2-layer LSTM decoder via FP16 tensor-core MMA. Round-17 = R16 (proven
// 1454us) + ldmatrix.x4 A-fragment loads (8 LDS.32 -> 2 LDSM per kc,
// conflict-free: row stride 1040B = 65*16B, 65 mod 8 = 1) + depth-3 cp.async
// ring (wait_group 2, prefetch distance 2 kc).
// 256 CTAs x 32 batch rows x 512 threads.
// ---------------------------------------------------------------------------

#define T_STEPS 20
#define AH 520     // A2 half-stride per row (1040B, 16B-aligned)
#define CS 264
#define PS 164

__device__ __forceinline__ float sigf(float x)  { return __fdividef(1.f, 1.f + __expf(-x)); }
__device__ __forceinline__ float tanhe(float x) { return __fdividef(2.f, 1.f + __expf(-2.f * x)) - 1.f; }
__device__ __forceinline__ void mma_f16(float* d, unsigned a0, unsigned a1, unsigned a2,
                                        unsigned a3, unsigned b0, unsigned b1) {
    asm volatile(
        "mma.sync.aligned.m16n8k16.row.col.f32.f16.f16.f32 "
        "{%0,%1,%2,%3}, {%4,%5,%6,%7}, {%8,%9}, {%0,%1,%2,%3};"
        : "+f"(d[0]), "+f"(d[1]), "+f"(d[2]), "+f"(d[3])
        : "r"(a0), "r"(a1), "r"(a2), "r"(a3), "r"(b0), "r"(b1));
}
__device__ __forceinline__ void lmx4(unsigned* a, unsigned saddr) {
    asm volatile("ldmatrix.sync.aligned.m8n8.x4.shared.b16 {%0,%1,%2,%3}, [%4];"
        : "=r"(a[0]), "=r"(a[1]), "=r"(a[2]), "=r"(a[3]) : "r"(saddr));
}
__device__ __forceinline__ void cpa16(unsigned dst, const void* src) {
    asm volatile("cp.async.cg.shared.global [%0], [%1], 16;" :: "r"(dst), "l"(src));
}
#define CP_COMMIT() asm volatile("cp.async.commit_group;")
#define CP_WAIT2()  asm volatile("cp.async.wait_group 2;")
#define CP_WAIT0()  asm volatile("cp.async.wait_group 0;")
__device__ __forceinline__ unsigned h2pack(float lo, float hi) {
    __half2 h = __floats2half2_rn(lo, hi);
    return *reinterpret_cast<unsigned*>(&h);
}

// GEMM weights, TILE-LINEAR fp16 layout (verified R16):
//   idx = kc*8192 + w*512 + j*128 + lane*4 + e      (kc covers K=16)
__device__ unsigned g_u1h [16 * 8192];      // U1 (16 kc)
__device__ unsigned g_w2h [32 * 8192];      // [W2;U2] (32 kc)
__device__ uint4    g_pwh [16 * 320];       // proj [kc][w(10)][lane]
__device__ float    g_b2p [1024];
__device__ float    g_pb  [160];
__device__ float4   g_w1q [64 * 256];
__device__ float    g_xw1p[8192u * 1024u];  // xw1 [row][n'] fp32

__global__ void repack_kernel(const float* __restrict__ W1, const float* __restrict__ U1,
                              const float* __restrict__ W2, const float* __restrict__ U2,
                              const float* __restrict__ Wmu, const float* __restrict__ Wlv,
                              const float* __restrict__ b2,  const float* __restrict__ bmu,
                              const float* __restrict__ blv) {
    int i = blockIdx.x * blockDim.x + threadIdx.x;   // 0 .. 524287
    if (i < 32 * 8192) {
        int kc   = i >> 13;
        int rem  = i & 8191;
        int w    = rem >> 9;
        int rem2 = rem & 511;
        int j    = rem2 >> 7;
        int le   = rem2 & 127;
        int lane = le >> 2, e = le & 3;
        int q    = lane & 3, lr = lane >> 2;
        int row  = kc * 16 + 2 * q + ((j >> 1) ? 8 : 0);
        int np   = w * 64 + (j & 1) * 32 + e * 8 + lr;
        int g = np & 3, u = np >> 2;
        if (kc < 16) {
            float lo = U1[row * 1024 + g * 256 + u];
            float hi = U1[(row + 1) * 1024 + g * 256 + u];
            g_u1h[i] = h2pack(lo, hi);
        }
        float lo, hi;
        if (row < 256) {
            lo = W2[row * 1024 + g * 256 + u];
            hi = W2[(row + 1) * 1024 + g * 256 + u];
        } else {
            lo = U2[(row - 256) * 1024 + g * 256 + u];
            hi = U2[(row - 255) * 1024 + g * 256 + u];
        }
        g_w2h[i] = h2pack(lo, hi);
    }
    if (i < 16 * 320) {
        int kc = i / 320, rem = i % 320;
        int w = rem / 32, lane = rem % 32;
        int q = lane & 3, lr = lane >> 2;
        uint4 v;
        #pragma unroll
        for (int nt = 0; nt < 2; nt++) {
            int col = w * 16 + nt * 8 + lr;
            const float* P = (col < 80) ? Wmu : Wlv;
            int f = (col < 80) ? col : col - 80;
            int r0 = kc * 16 + 2 * q;
            unsigned v0 = h2pack(P[r0 * 80 + f],       P[(r0 + 1) * 80 + f]);
            unsigned v1 = h2pack(P[(r0 + 8) * 80 + f], P[(r0 + 9) * 80 + f]);
            if (nt == 0) { v.x = v0; v.z = v1; } else { v.y = v0; v.w = v1; }
        }
        g_pwh[i] = v;
    }
    if (i < 64 * 256) {
        const float* r = W1 + (i >> 8) * 1024;
        int uu = i & 255;
        g_w1q[i] = make_float4(r[uu], r[256 + uu], r[512 + uu], r[768 + uu]);
    }
    if (i < 1024) g_b2p[i] = b2[(i & 3) * 256 + (i >> 2)];
    if (i < 160)  g_pb[i]  = (i < 80) ? bmu[i] : blv[i - 80];
}

__global__ void xw1_kernel(const float* __restrict__ z1, const float* __restrict__ z2,
                           const float* __restrict__ b1) {
    __shared__ float zt[8][64];
    const int tid = threadIdx.x;
    const int rb  = blockIdx.x * 8;
    for (int i = tid; i < 512; i += 256) {
        int r = i >> 6, k = i & 63;
        zt[r][k] = (k < 32) ? z1[(rb + r) * 32 + k] : z2[(rb + r) * 32 + (k - 32)];
    }
    __syncthreads();
    const int u = tid;
    float4 acc[8];
    #pragma unroll
    for (int r = 0; r < 8; r++) acc[r] = make_float4(0.f, 0.f, 0.f, 0.f);
    for (int k = 0; k < 64; k++) {
        float4 w = g_w1q[k * 256 + u];
        #pragma unroll
        for (int r = 0; r < 8; r++) {
            float zv = zt[r][k];
            acc[r].x += zv * w.x; acc[r].y += zv * w.y;
            acc[r].z += zv * w.z; acc[r].w += zv * w.w;
        }
    }
    float4 bq = make_float4(b1[u], b1[256 + u], b1[512 + u], b1[768 + u]);
    #pragma unroll
    for (int r = 0; r < 8; r++) {
        float4 o = make_float4(acc[r].x + bq.x, acc[r].y + bq.y,
                               acc[r].z + bq.z, acc[r].w + bq.w);
        *(float4*)(g_xw1p + (size_t)(rb + r) * 1024 + 4 * u) = o;
    }
}

// SMEM: A2h [32][AH] halves | c1s/c2s [32][CS] | prj [32][PS] | 3x32KB stages
#define A2_FLOATS  (32 * AH / 2)
#define SMEM_CORE  (A2_FLOATS + 2 * 32 * CS + 32 * PS)
#define SMEM_FLOATS (SMEM_CORE + 3 * 8192)
#define SMEM_BYTES  (SMEM_FLOATS * 4)

// Pipelined GEMM with ldmatrix A-frags and depth-3 ring.
// aS0/aS1: per-lane ldmatrix base shared-addrs (bytes) for mt=0/1 row blocks.
__device__ __forceinline__ void gemm_pipe(
    float acc[8][2][4], unsigned aS0, unsigned aS1,
    const unsigned* __restrict__ B, int KC,
    unsigned sdst, int w, int lane)
{
    const unsigned* gsrc = B + w * 512 + lane * 4;

    #pragma unroll
    for (int s = 0; s < 3; s++) {
        const unsigned* src = gsrc + s * 8192;
        unsigned dst = sdst + s * 32768;
        #pragma unroll
        for (int p = 0; p < 4; p++)
            cpa16(dst + p * 512, src + p * 128);
        CP_COMMIT();
    }

    unsigned bufoff = 0;
    #pragma unroll 1
    for (int kc = 0; kc < KC; kc++) {
        CP_WAIT2();
        unsigned sbuf = sdst + bufoff;
        uint4 b0A, b0B, b1A, b1B;
        asm volatile("ld.shared.v4.u32 {%0,%1,%2,%3}, [%4];"
            : "=r"(b0A.x), "=r"(b0A.y), "=r"(b0A.z), "=r"(b0A.w) : "r"(sbuf));
        asm volatile("ld.shared.v4.u32 {%0,%1,%2,%3}, [%4];"
            : "=r"(b0B.x), "=r"(b0B.y), "=r"(b0B.z), "=r"(b0B.w) : "r"(sbuf + 512));
        asm volatile("ld.shared.v4.u32 {%0,%1,%2,%3}, [%4];"
            : "=r"(b1A.x), "=r"(b1A.y), "=r"(b1A.z), "=r"(b1A.w) : "r"(sbuf + 1024));
        asm volatile("ld.shared.v4.u32 {%0,%1,%2,%3}, [%4];"
            : "=r"(b1B.x), "=r"(b1B.y), "=r"(b1B.z), "=r"(b1B.w) : "r"(sbuf + 1536));
        if (kc + 3 < KC) {
            const unsigned* src = gsrc + (size_t)(kc + 3) * 8192;
            #pragma unroll
            for (int p = 0; p < 4; p++)
                cpa16(sbuf + p * 512, src + p * 128);
        }
        CP_COMMIT();
        bufoff = (bufoff == 65536) ? 0 : bufoff + 32768;

        unsigned a[2][4];
        lmx4(a[0], aS0 + kc * 32);      // kb*2 bytes = kc*16*2
        lmx4(a[1], aS1 + kc * 32);
        #pragma unroll
        for (int mt = 0; mt < 2; mt++) {
            mma_f16(acc[0][mt], a[mt][0], a[mt][1], a[mt][2], a[mt][3], b0A.x, b1A.x);
            mma_f16(acc[1][mt], a[mt][0], a[mt][1], a[mt][2], a[mt][3], b0A.y, b1A.y);
            mma_f16(acc[2][mt], a[mt][0], a[mt][1], a[mt][2], a[mt][3], b0A.z, b1A.z);
            mma_f16(acc[3][mt], a[mt][0], a[mt][1], a[mt][2], a[mt][3], b0A.w, b1A.w);
            mma_f16(acc[4][mt], a[mt][0], a[mt][1], a[mt][2], a[mt][3], b0B.x, b1B.x);
            mma_f16(acc[5][mt], a[mt][0], a[mt][1], a[mt][2], a[mt][3], b0B.y, b1B.y);
            mma_f16(acc[6][mt], a[mt][0], a[mt][1], a[mt][2], a[mt][3], b0B.z, b1B.z);
            mma_f16(acc[7][mt], a[mt][0], a[mt][1], a[mt][2], a[mt][3], b0B.w, b1B.w);
        }
    }
    CP_WAIT0();
}

__global__ void __launch_bounds__(512, 1) lstm_kernel(
    const float* __restrict__ eps, float* __restrict__ out)
{
    extern __shared__ float sm[];
    __half* A2h = (__half*)sm;              // [32][AH] halves
    float* c1s = sm + A2_FLOATS;            // [32][CS]
    float* c2s = c1s + 32 * CS;
    float* prj = c2s + 32 * CS;             // [32][PS]
    float* stg = sm + SMEM_CORE;
    const unsigned sbase = (unsigned)__cvta_generic_to_shared(stg);

    const int tid  = threadIdx.x;
    const int w    = tid >> 5;          // 0..15
    const int lane = tid & 31;
    const int q    = lane & 3;
    const int lr   = lane >> 2;
    const int rb   = blockIdx.x * 32;
    const int wb   = w * 64;
    const bool qe  = !(q & 1);
    const unsigned sdst = sbase + w * 2048 + lane * 16;

    // ldmatrix bases: row = mt*16 + (lane&15), k-offset = (lane>>4)*8 halves
    const int arow  = lane & 15;
    const int koff8 = (lane >> 4) * 8;
    const unsigned aS0 = (unsigned)__cvta_generic_to_shared(A2h + arow * AH + koff8);
    const unsigned aS1 = (unsigned)__cvta_generic_to_shared(A2h + (16 + arow) * AH + koff8);

    for (int i = tid; i < SMEM_CORE; i += 512) sm[i] = 0.f;
    __syncthreads();

    float acc[8][2][4];

    for (int t = 0; t < T_STEPS; t++) {
        // ===================== GEMM1: h1old @ U1 =====================
        #pragma unroll
        for (int nt = 0; nt < 8; nt++)
            #pragma unroll
            for (int mt = 0; mt < 2; mt++)
                acc[nt][mt][0] = acc[nt][mt][1] = acc[nt][mt][2] = acc[nt][mt][3] = 0.f;
        gemm_pipe(acc, aS0, aS1, g_u1h, 16, sdst, w, lane);
        __syncthreads();                                 // (1) A2 h1 reads done

        // ----- epilogue 1: + xw1, gates, c1/h1 update -----
        #pragma unroll
        for (int nt = 0; nt < 8; nt++) {
            #pragma unroll
            for (int mt = 0; mt < 2; mt++) {
                float* d = acc[nt][mt];
                int cb = wb + nt * 8 + q * 2;
                int R0 = mt * 16 + lr, R1 = R0 + 8;
                float2 x0 = *(const float2*)(g_xw1p + (size_t)(rb + R0) * 1024 + cb);
                float2 x1 = *(const float2*)(g_xw1p + (size_t)(rb + R1) * 1024 + cb);
                d[0] += x0.x; d[1] += x0.y; d[2] += x1.x; d[3] += x1.y;
                float s0, s1, s2, s3;
                if (q & 1) { s0 = tanhe(d[0]); s1 = sigf(d[1]); s2 = tanhe(d[2]); s3 = sigf(d[3]); }
                else       { s0 = sigf(d[0]);  s1 = sigf(d[1]); s2 = sigf(d[2]);  s3 = sigf(d[3]); }
                float r0 = __shfl_xor_sync(~0u, s0, 1);
                float r1 = __shfl_xor_sync(~0u, s1, 1);
                float r2 = __shfl_xor_sync(~0u, s2, 1);
                float r3 = __shfl_xor_sync(~0u, s3, 1);
                if (qe) {   // owns (i,f); receives (g,o)
                    int u = w * 16 + nt * 2 + (q >> 1);
                    float cn0 = s1 * c1s[R0 * CS + u] + s0 * r0;
                    c1s[R0 * CS + u] = cn0;
                    A2h[R0 * AH + u] = __float2half_rn(r1 * tanhe(cn0));
                    float cn1 = s3 * c1s[R1 * CS + u] + s2 * r2;
                    c1s[R1 * CS + u] = cn1;
                    A2h[R1 * AH + u] = __float2half_rn(r3 * tanhe(cn1));
                }
            }
        }
        __syncthreads();                                 // (2) h1new visible

        // ============ GEMM2: [h1new|h2old] @ [W2;U2] ============
        #pragma unroll
        for (int nt = 0; nt < 8; nt++)
            #pragma unroll
            for (int mt = 0; mt < 2; mt++)
                acc[nt][mt][0] = acc[nt][mt][1] = acc[nt][mt][2] = acc[nt][mt][3] = 0.f;
        gemm_pipe(acc, aS0, aS1, g_w2h, 32, sdst, w, lane);
        __syncthreads();                                 // (3) A2 reads done

        // ----- epilogue 2: + b2, gates, c2/h2 update, h2 -> out -----
        #pragma unroll
        for (int nt = 0; nt < 8; nt++) {
            #pragma unroll
            for (int mt = 0; mt < 2; mt++) {
                float* d = acc[nt][mt];
                int cb = wb + nt * 8 + q * 2;
                int R0 = mt * 16 + lr, R1 = R0 + 8;
                float2 bb = *(const float2*)(g_b2p + cb);
                d[0] += bb.x; d[1] += bb.y; d[2] += bb.x; d[3] += bb.y;
                float s0, s1, s2, s3;
                if (q & 1) { s0 = tanhe(d[0]); s1 = sigf(d[1]); s2 = tanhe(d[2]); s3 = sigf(d[3]); }
                else       { s0 = sigf(d[0]);  s1 = sigf(d[1]); s2 = sigf(d[2]);  s3 = sigf(d[3]); }
                float r0 = __shfl_xor_sync(~0u, s0, 1);
                float r1 = __shfl_xor_sync(~0u, s1, 1);
                float r2 = __shfl_xor_sync(~0u, s2, 1);
                float r3 = __shfl_xor_sync(~0u, s3, 1);
                if (qe) {
                    int u = w * 16 + nt * 2 + (q >> 1);
                    float cn0 = s1 * c2s[R0 * CS + u] + s0 * r0;
                    c2s[R0 * CS + u] = cn0;
                    float h0 = r1 * tanhe(cn0);
                    A2h[R0 * AH + 256 + u] = __float2half_rn(h0);
                    float cn1 = s3 * c2s[R1 * CS + u] + s2 * r2;
                    c2s[R1 * CS + u] = cn1;
                    float h1 = r3 * tanhe(cn1);
                    A2h[R1 * AH + 256 + u] = __float2half_rn(h1);
                    out[((size_t)(rb + R0) * T_STEPS + t) * 256 + u] = h0;
                    out[((size_t)(rb + R1) * T_STEPS + t) * 256 + u] = h1;
                }
            }
        }
        __syncthreads();                                 // (4) h2new visible

        // =============== PROJ: h2new @ [Wmu|Wlv] (warps 0-9) ===============
        if (w < 10) {
            float pa[2][2][4];
            #pragma unroll
            for (int nt = 0; nt < 2; nt++)
                #pragma unroll
                for (int mt = 0; mt < 2; mt++)
                    pa[nt][mt][0] = pa[nt][mt][1] = pa[nt][mt][2] = pa[nt][mt][3] = 0.f;
            #pragma unroll 2
            for (int kc = 0; kc < 16; kc++) {
                uint4 bv = g_pwh[kc * 320 + w * 32 + lane];
                unsigned a[2][4];
                lmx4(a[0], aS0 + 512 + kc * 32);     // acol 256 halves = 512 bytes
                lmx4(a[1], aS1 + 512 + kc * 32);
                #pragma unroll
                for (int mt = 0; mt < 2; mt++) {
                    mma_f16(pa[0][mt], a[mt][0], a[mt][1], a[mt][2], a[mt][3], bv.x, bv.z);
                    mma_f16(pa[1][mt], a[mt][0], a[mt][1], a[mt][2], a[mt][3], bv.y, bv.w);
                }
            }
            #pragma unroll
            for (int nt = 0; nt < 2; nt++) {
                #pragma unroll
                for (int mt = 0; mt < 2; mt++) {
                    int col = w * 16 + nt * 8 + q * 2;
                    int R0 = mt * 16 + lr, R1 = R0 + 8;
                    float2 pb = *(const float2*)(g_pb + col);
                    prj[R0 * PS + col]     = pa[nt][mt][0] + pb.x;
                    prj[R0 * PS + col + 1] = pa[nt][mt][1] + pb.y;
                    prj[R1 * PS + col]     = pa[nt][mt][2] + pb.x;
                    prj[R1 * PS + col + 1] = pa[nt][mt][3] + pb.y;
                }
            }
        }
        __syncthreads();                                 // (5) prj ready

        // ---- sampler ----
        #pragma unroll
        for (int j = 0; j < 5; j++) {
            int i = tid + j * 512;
            int r = i / 80, f = i - r * 80;
            float mu = prj[r * PS + f];
            float lv = prj[r * PS + f + 80];
            size_t base = ((size_t)(rb + r) * T_STEPS + t) * 80 + f;
            float e = eps[base];
            out[41943040u + base] = mu;
            out[55050240u + base] = lv;
            out[68157440u + base] = e * __expf(0.5f * mu) + lv;
        }
    }
}

extern "C" void kernel_launch(void* const* d_in, const int* in_sizes, int n_in,
                              void* d_out, int out_size) {
    // order: x, z1, z2, eps, W1, U1, b1, W2, U2, b2, Wmu, bmu, Wlv, blv
    const float* z1  = (const float*)d_in[1];
    const float* z2  = (const float*)d_in[2];
    const float* eps = (const float*)d_in[3];
    const float* W1  = (const float*)d_in[4];
    const float* U1  = (const float*)d_in[5];
    const float* b1  = (const float*)d_in[6];
    const float* W2  = (const float*)d_in[7];
    const float* U2  = (const float*)d_in[8];
    const float* b2  = (const float*)d_in[9];
    const float* Wmu = (const float*)d_in[10];
    const float* bmu = (const float*)d_in[11];
    const float* Wlv = (const float*)d_in[12];
    const float* blv = (const float*)d_in[13];
    float* out = (float*)d_out;

    cudaFuncSetAttribute(lstm_kernel, cudaFuncAttributeMaxDynamicSharedMemorySize, SMEM_BYTES);

    repack_kernel<<<512, 1024>>>(W1, U1, W2, U2, Wmu, Wlv, b2, bmu, blv);
    xw1_kernel<<<1024, 256>>>(z1, z2, b1);
    lstm_kernel<<<256, 512, SMEM_BYTES>>>(eps, out);
}